// round 12
// baseline (speedup 1.0000x reference)
#include <cuda_runtime.h>
#include <math.h>

// ---------------------------------------------------------------------------
// QuantBasicBlock: conv1(3x3,s2)+BN+ReLU+BFPq -> conv2(3x3,s1)+BN
//                  + shortcut(1x1,s2)+BN -> add -> ReLU -> BFPq
// Shapes: x(64,128,56,56), w1(256,128,3,3), w2(256,256,3,3), ws(256,128,1,1)
// out (64,256,28,28) fp32
// ---------------------------------------------------------------------------

#define NB    64
#define CIN1  128
#define COUT  256
#define HOUT  28
#define HW    (HOUT*HOUT)
#define BN_EPS 1e-5f

// Scratch (static device allocations; no cudaMalloc allowed)
__device__ float g_wq1[CIN1 * 9 * COUT];   // quantized w1, layout [ic*9+tap][oc]
__device__ float g_wq2[COUT * 9 * COUT];   // quantized w2, layout [ic*9+tap][oc]
__device__ float g_wqs[CIN1 * COUT];       // quantized ws, layout [ic][oc]
__device__ float g_buf1[(size_t)NB * COUT * HW];  // conv1 output / quantized act
__device__ float g_buf2[(size_t)NB * COUT * HW];  // conv2 output / residual sum

// ---------------------------------------------------------------------------
// Weight quantization (DSConv VQK): per (oc, 32-ic block, tap) scale = max/127,
// q = clip(rint(w/scale), -128, 127), store q*scale TRANSPOSED to [ic*9+tap][oc]
// ---------------------------------------------------------------------------
__global__ __launch_bounds__(256)
void quant_w3x3(const float* __restrict__ w, float* __restrict__ wq, int I, int O)
{
    int tid = blockIdx.x * blockDim.x + threadIdx.x;
    int IB = I / 32;
    int total = O * IB * 9;
    if (tid >= total) return;
    int tap = tid % 9;
    int ib  = (tid / 9) % IB;
    int o   = tid / (9 * IB);

    float v[32];
    float m = 0.f;
#pragma unroll
    for (int c = 0; c < 32; c++) {
        v[c] = w[((size_t)(o * I + ib * 32 + c)) * 9 + tap];
        m = fmaxf(m, fabsf(v[c]));
    }
    float scale = fmaxf(m, 1e-12f) * (1.0f / 127.0f);
#pragma unroll
    for (int c = 0; c < 32; c++) {
        float q = rintf(v[c] / scale);
        q = fminf(fmaxf(q, -128.f), 127.f);
        wq[((size_t)(ib * 32 + c) * 9 + tap) * O + o] = q * scale;
    }
}

__global__ __launch_bounds__(256)
void quant_w1x1(const float* __restrict__ w, float* __restrict__ wq)
{
    int tid = blockIdx.x * blockDim.x + threadIdx.x;   // over COUT * (CIN1/32)
    if (tid >= COUT * (CIN1 / 32)) return;
    int ib = tid % (CIN1 / 32);
    int o  = tid / (CIN1 / 32);

    float v[32];
    float m = 0.f;
#pragma unroll
    for (int c = 0; c < 32; c++) {
        v[c] = w[o * CIN1 + ib * 32 + c];
        m = fmaxf(m, fabsf(v[c]));
    }
    float scale = fmaxf(m, 1e-12f) * (1.0f / 127.0f);
#pragma unroll
    for (int c = 0; c < 32; c++) {
        float q = rintf(v[c] / scale);
        q = fminf(fmaxf(q, -128.f), 127.f);
        wq[(ib * 32 + c) * COUT + o] = q * scale;
    }
}

// ---------------------------------------------------------------------------
// 3x3 conv + BN (+optional ReLU).
// Block = 128 threads computes tile: 128 oc x 28 w x 1 h x 1 n.
// Thread t: oc = oc_base + (t&31) + 32*j (j=0..3), w = (t>>5)*7 + i (i=0..6)
// ic chunks of 4 via shared memory. Weight layout is pre-transposed [ic*9+tap][oc].
// ---------------------------------------------------------------------------
template <int STRIDE>
__global__ __launch_bounds__(128)
void conv3x3_bn(const float* __restrict__ x, const float* __restrict__ wq,
                const float* __restrict__ bg, const float* __restrict__ bb,
                const float* __restrict__ bm, const float* __restrict__ bv,
                float* __restrict__ out, int CIN, int HIN, int RELU)
{
    constexpr int IWB = (STRIDE == 2) ? 57 : 30;   // input cols needed (+pad)
    __shared__ float s_w[4 * 9 * 128];
    __shared__ float s_in[4 * 3 * IWB];

    const int t       = threadIdx.x;
    const int oc_base = blockIdx.x * 128;
    const int h       = blockIdx.y;
    const int n       = blockIdx.z;
    const int oc_lane = t & 31;
    const int wbase   = (t >> 5) * 7;
    const int WIN     = HIN;

    float acc[4][7];
#pragma unroll
    for (int j = 0; j < 4; j++)
#pragma unroll
        for (int i = 0; i < 7; i++) acc[j][i] = 0.f;

    for (int ic0 = 0; ic0 < CIN; ic0 += 4) {
        __syncthreads();
        // weights: 4 ic x 9 taps x 128 oc  (coalesced: global is [tap][oc])
        const float* wg = wq + (size_t)ic0 * 9 * COUT + oc_base;
#pragma unroll
        for (int k = 0; k < 36; k++) {
            int idx = k * 128 + t;
            s_w[idx] = wg[(size_t)(idx >> 7) * COUT + (idx & 127)];
        }
        // input patch: 4 ic x 3 rows x IWB cols (zero-padded)
        for (int idx = t; idx < 4 * 3 * IWB; idx += 128) {
            int icc = idx / (3 * IWB);
            int rem = idx - icc * 3 * IWB;
            int r   = rem / IWB;
            int jj  = rem - r * IWB;
            int ih  = h * STRIDE + r - 1;
            int iw  = jj - 1;
            float val = 0.f;
            if (ih >= 0 && ih < HIN && iw >= 0 && iw < WIN)
                val = x[(((size_t)n * CIN + ic0 + icc) * HIN + ih) * WIN + iw];
            s_in[idx] = val;
        }
        __syncthreads();

        for (int icc = 0; icc < 4; icc++) {
#pragma unroll
            for (int kh = 0; kh < 3; kh++) {
#pragma unroll
                for (int kw = 0; kw < 3; kw++) {
                    const int tap = icc * 9 + kh * 3 + kw;
                    float wv0 = s_w[tap * 128 + oc_lane];
                    float wv1 = s_w[tap * 128 + oc_lane + 32];
                    float wv2 = s_w[tap * 128 + oc_lane + 64];
                    float wv3 = s_w[tap * 128 + oc_lane + 96];
                    const float* sp = &s_in[icc * 3 * IWB + kh * IWB + wbase * STRIDE + kw];
#pragma unroll
                    for (int i = 0; i < 7; i++) {
                        float xv = sp[i * STRIDE];
                        acc[0][i] += wv0 * xv;
                        acc[1][i] += wv1 * xv;
                        acc[2][i] += wv2 * xv;
                        acc[3][i] += wv3 * xv;
                    }
                }
            }
        }
    }

    // epilogue: BN (+ReLU)
#pragma unroll
    for (int j = 0; j < 4; j++) {
        int oc = oc_base + oc_lane + 32 * j;
        float inv  = bg[oc] * rsqrtf(bv[oc] + BN_EPS);
        float beta = bb[oc] - bm[oc] * inv;
        size_t base = (((size_t)n * COUT + oc) * HOUT + h) * HOUT + wbase;
#pragma unroll
        for (int i = 0; i < 7; i++) {
            float val = acc[j][i] * inv + beta;
            if (RELU) val = fmaxf(val, 0.f);
            out[base + i] = val;
        }
    }
}

// ---------------------------------------------------------------------------
// Shortcut: 1x1 conv stride 2 + BN, fused with residual add + ReLU into buf2.
// Block = (h, n), 256 threads, thread t = oc; 28 w accumulators.
// ---------------------------------------------------------------------------
__global__ __launch_bounds__(256)
void shortcut_bn_add(const float* __restrict__ x, const float* __restrict__ wq,
                     const float* __restrict__ bg, const float* __restrict__ bb,
                     const float* __restrict__ bm, const float* __restrict__ bv,
                     float* __restrict__ buf)
{
    __shared__ float s_x[CIN1 * HOUT];   // 128 ic x 28 w
    const int t = threadIdx.x;
    const int h = blockIdx.x;
    const int n = blockIdx.y;

    for (int idx = t; idx < CIN1 * HOUT; idx += 256) {
        int i = idx / HOUT;
        int w = idx - i * HOUT;
        s_x[idx] = x[(((size_t)n * CIN1 + i) * 56 + 2 * h) * 56 + 2 * w];
    }
    __syncthreads();

    const int oc = t;
    float acc[HOUT];
#pragma unroll
    for (int w = 0; w < HOUT; w++) acc[w] = 0.f;

    for (int i = 0; i < CIN1; i++) {
        float wv = wq[i * COUT + oc];
        const float* sp = &s_x[i * HOUT];
#pragma unroll
        for (int w = 0; w < HOUT; w++) acc[w] += wv * sp[w];
    }

    float inv  = bg[oc] * rsqrtf(bv[oc] + BN_EPS);
    float beta = bb[oc] - bm[oc] * inv;
    size_t base = (((size_t)n * COUT + oc) * HOUT + h) * HOUT;
#pragma unroll
    for (int w = 0; w < HOUT; w++) {
        float val = buf[base + w] + acc[w] * inv + beta;
        buf[base + w] = fmaxf(val, 0.f);
    }
}

// ---------------------------------------------------------------------------
// BFP activation quant: per (n, 32-channel block, h, w): shared power-of-2
// exponent, 8-bit mantissa. e = floor(log2(max(|x|,1e-12))) computed exactly
// via frexpf; scale = 2^(e-6); q = clip(rint(x/scale), -128, 127); out = q*scale
// ---------------------------------------------------------------------------
__global__ __launch_bounds__(256)
void bfp_quant(const float* __restrict__ in, float* __restrict__ out)
{
    int tid = blockIdx.x * 256 + threadIdx.x;   // exactly NB*8*HW threads
    int hw = tid % HW;
    int cb = (tid / HW) & 7;
    int n  = tid / (HW * 8);

    size_t base = (((size_t)n * COUT + cb * 32) * HW) + hw;
    float v[32];
    float m = 0.f;
#pragma unroll
    for (int c = 0; c < 32; c++) {
        v[c] = in[base + (size_t)c * HW];
        m = fmaxf(m, fabsf(v[c]));
    }
    m = fmaxf(m, 1e-12f);
    int e;
    frexpf(m, &e);                       // m = f*2^e, f in [0.5,1) -> floor(log2 m)=e-1
    float scale = ldexpf(1.0f, e - 7);   // 2^(floor(log2 m) + 1 - 7)
#pragma unroll
    for (int c = 0; c < 32; c++) {
        float q = rintf(v[c] / scale);
        q = fminf(fmaxf(q, -128.f), 127.f);
        out[base + (size_t)c * HW] = q * scale;
    }
}

// ---------------------------------------------------------------------------
extern "C" void kernel_launch(void* const* d_in, const int* in_sizes, int n_in,
                              void* d_out, int out_size)
{
    const float* x  = (const float*)d_in[0];
    const float* w1 = (const float*)d_in[1];
    const float* w2 = (const float*)d_in[2];
    const float* ws = (const float*)d_in[3];
    const float* bn1_g = (const float*)d_in[4];
    const float* bn1_b = (const float*)d_in[5];
    const float* bn1_m = (const float*)d_in[6];
    const float* bn1_v = (const float*)d_in[7];
    const float* bn2_g = (const float*)d_in[8];
    const float* bn2_b = (const float*)d_in[9];
    const float* bn2_m = (const float*)d_in[10];
    const float* bn2_v = (const float*)d_in[11];
    const float* bns_g = (const float*)d_in[12];
    const float* bns_b = (const float*)d_in[13];
    const float* bns_m = (const float*)d_in[14];
    const float* bns_v = (const float*)d_in[15];
    float* out = (float*)d_out;

    float *wq1, *wq2, *wqs, *buf1, *buf2;
    cudaGetSymbolAddress((void**)&wq1,  g_wq1);
    cudaGetSymbolAddress((void**)&wq2,  g_wq2);
    cudaGetSymbolAddress((void**)&wqs,  g_wqs);
    cudaGetSymbolAddress((void**)&buf1, g_buf1);
    cudaGetSymbolAddress((void**)&buf2, g_buf2);

    // 1. weight quantization (+ transpose to [ic*9+tap][oc])
    quant_w3x3<<<(COUT * (CIN1/32) * 9 + 255) / 256, 256>>>(w1, wq1, CIN1, COUT);
    quant_w3x3<<<(COUT * (COUT/32) * 9 + 255) / 256, 256>>>(w2, wq2, COUT, COUT);
    quant_w1x1<<<(COUT * (CIN1/32) + 255) / 256, 256>>>(ws, wqs);

    // 2. conv1 (3x3, stride 2) + BN1 + ReLU
    conv3x3_bn<2><<<dim3(COUT/128, HOUT, NB), 128>>>(
        x, wq1, bn1_g, bn1_b, bn1_m, bn1_v, buf1, CIN1, 56, 1);

    // 3. BFP activation quant (in-place)
    bfp_quant<<<(NB * 8 * HW) / 256, 256>>>(buf1, buf1);

    // 4. conv2 (3x3, stride 1) + BN2
    conv3x3_bn<1><<<dim3(COUT/128, HOUT, NB), 128>>>(
        buf1, wq2, bn2_g, bn2_b, bn2_m, bn2_v, buf2, COUT, HOUT, 0);

    // 5. shortcut 1x1 stride-2 conv + BNs + add + ReLU (into buf2)
    shortcut_bn_add<<<dim3(HOUT, NB), 256>>>(
        x, wqs, bns_g, bns_b, bns_m, bns_v, buf2);

    // 6. final BFP activation quant -> out
    bfp_quant<<<(NB * 8 * HW) / 256, 256>>>(buf2, out);
}

// round 13
// speedup vs baseline: 1.0945x; 1.0945x over previous
#include <cuda_runtime.h>
#include <math.h>

// ---------------------------------------------------------------------------
// QuantBasicBlock: conv1(3x3,s2)+BN+ReLU+BFPq -> conv2(3x3,s1)+BN
//                  + shortcut(1x1,s2)+BN -> add -> ReLU -> BFPq
// Shapes: x(64,128,56,56), w1(256,128,3,3), w2(256,256,3,3), ws(256,128,1,1)
// out (64,256,28,28) fp32
// ---------------------------------------------------------------------------

#define NB    64
#define CIN1  128
#define COUT  256
#define HOUT  28
#define HW    (HOUT*HOUT)
#define BN_EPS 1e-5f

// Scratch (static device allocations; no cudaMalloc allowed)
__device__ __align__(16) float g_wq1[CIN1 * 9 * COUT];   // [ic*9+tap][oc]
__device__ __align__(16) float g_wq2[COUT * 9 * COUT];   // [ic*9+tap][oc]
__device__ __align__(16) float g_wqs[CIN1 * COUT];       // [ic][oc]
__device__ float g_buf1[(size_t)NB * COUT * HW];
__device__ float g_buf2[(size_t)NB * COUT * HW];

// ---------------------------------------------------------------------------
// Weight quantization (DSConv VQK): per (oc, 32-ic block, tap) scale = max/127,
// q = clip(rint(w/scale), -128, 127), store q*scale TRANSPOSED to [ic*9+tap][oc]
// ---------------------------------------------------------------------------
__global__ __launch_bounds__(256)
void quant_w3x3(const float* __restrict__ w, float* __restrict__ wq, int I, int O)
{
    int tid = blockIdx.x * blockDim.x + threadIdx.x;
    int IB = I / 32;
    int total = O * IB * 9;
    if (tid >= total) return;
    int tap = tid % 9;
    int ib  = (tid / 9) % IB;
    int o   = tid / (9 * IB);

    float v[32];
    float m = 0.f;
#pragma unroll
    for (int c = 0; c < 32; c++) {
        v[c] = w[((size_t)(o * I + ib * 32 + c)) * 9 + tap];
        m = fmaxf(m, fabsf(v[c]));
    }
    float scale = fmaxf(m, 1e-12f) * (1.0f / 127.0f);
#pragma unroll
    for (int c = 0; c < 32; c++) {
        float q = rintf(v[c] / scale);
        q = fminf(fmaxf(q, -128.f), 127.f);
        wq[((size_t)(ib * 32 + c) * 9 + tap) * O + o] = q * scale;
    }
}

__global__ __launch_bounds__(256)
void quant_w1x1(const float* __restrict__ w, float* __restrict__ wq)
{
    int tid = blockIdx.x * blockDim.x + threadIdx.x;
    if (tid >= COUT * (CIN1 / 32)) return;
    int ib = tid % (CIN1 / 32);
    int o  = tid / (CIN1 / 32);

    float v[32];
    float m = 0.f;
#pragma unroll
    for (int c = 0; c < 32; c++) {
        v[c] = w[o * CIN1 + ib * 32 + c];
        m = fmaxf(m, fabsf(v[c]));
    }
    float scale = fmaxf(m, 1e-12f) * (1.0f / 127.0f);
#pragma unroll
    for (int c = 0; c < 32; c++) {
        float q = rintf(v[c] / scale);
        q = fminf(fmaxf(q, -128.f), 127.f);
        wq[(ib * 32 + c) * COUT + o] = q * scale;
    }
}

// ---------------------------------------------------------------------------
// 3x3 conv + BN (+optional ReLU), 512 threads/block.
// Tile: 128 oc x 28 w x 4 h x 1 n. Warp w: hsub = w>>2, wgroup = w&3 (7 cols).
// Thread: 4 CONSECUTIVE oc (one LDS.128 per tap) x 7 w. Input window kept in
// registers per (icc,kh), reused across all 3 kw.
// Weight layout pre-transposed to [ic*9+tap][oc] -> vectorized smem fill.
// ---------------------------------------------------------------------------
template <int STRIDE, int CIN>
__global__ __launch_bounds__(512, 2)
void conv3x3_bn(const float* __restrict__ x, const float* __restrict__ wq,
                const float* __restrict__ bg, const float* __restrict__ bb,
                const float* __restrict__ bm, const float* __restrict__ bv,
                float* __restrict__ out, int HIN, int RELU)
{
    constexpr int ROWS = 3 * STRIDE + 3;              // input rows per tile
    constexpr int IWB  = (STRIDE == 2) ? 57 : 30;     // valid input cols (+pad)
    constexpr int IWP  = (STRIDE == 2) ? 60 : 32;     // padded row pitch
    constexpr int WSZ  = 6 * STRIDE + 3;              // register window size

    __shared__ float4 s_w4[4 * 9 * 32];               // 4 ic x 9 taps x 128 oc
    __shared__ float  s_in[4 * ROWS * IWP];

    const int t       = threadIdx.x;
    const int lane    = t & 31;
    const int warp    = t >> 5;
    const int hsub    = warp >> 2;
    const int wbase   = (warp & 3) * 7;
    const int oc_base = blockIdx.x * 128;
    const int h0      = blockIdx.y * 4;
    const int n       = blockIdx.z;
    const int WIN     = HIN;

    float4 acc[7];
#pragma unroll
    for (int i = 0; i < 7; i++) acc[i] = make_float4(0.f, 0.f, 0.f, 0.f);

    const float4* wq4 = (const float4*)wq;

    for (int ic0 = 0; ic0 < CIN; ic0 += 4) {
        __syncthreads();
        // weights: 36 rows of 128 floats each (coalesced float4)
        for (int k = t; k < 4 * 9 * 32; k += 512) {
            int row = k >> 5;
            int c4  = k & 31;
            s_w4[k] = wq4[(size_t)(ic0 * 9 + row) * (COUT / 4) + (oc_base >> 2) + c4];
        }
        // input patch: 4 ic x ROWS x IWB cols (zero-padded halo)
        for (int idx = t; idx < 4 * ROWS * IWB; idx += 512) {
            int icc = idx / (ROWS * IWB);
            int rem = idx - icc * (ROWS * IWB);
            int r   = rem / IWB;
            int j   = rem - r * IWB;
            int ih  = h0 * STRIDE + r - 1;
            int iw  = j - 1;
            float val = 0.f;
            if (ih >= 0 && ih < HIN && iw >= 0 && iw < WIN)
                val = x[(((size_t)n * CIN + ic0 + icc) * HIN + ih) * WIN + iw];
            s_in[(icc * ROWS + r) * IWP + j] = val;
        }
        __syncthreads();

#pragma unroll
        for (int icc = 0; icc < 4; icc++) {
#pragma unroll
            for (int kh = 0; kh < 3; kh++) {
                const float* sp =
                    &s_in[(icc * ROWS + hsub * STRIDE + kh) * IWP + wbase * STRIDE];
                float win[WSZ];
#pragma unroll
                for (int j = 0; j < WSZ; j++) win[j] = sp[j];
#pragma unroll
                for (int kw = 0; kw < 3; kw++) {
                    float4 wv = s_w4[(icc * 9 + kh * 3 + kw) * 32 + lane];
#pragma unroll
                    for (int i = 0; i < 7; i++) {
                        float xv = win[i * STRIDE + kw];
                        acc[i].x += wv.x * xv;
                        acc[i].y += wv.y * xv;
                        acc[i].z += wv.z * xv;
                        acc[i].w += wv.w * xv;
                    }
                }
            }
        }
    }

    // epilogue: BN (+ReLU)
    const int h = h0 + hsub;
#pragma unroll
    for (int j = 0; j < 4; j++) {
        int oc = oc_base + lane * 4 + j;
        float inv  = bg[oc] * rsqrtf(bv[oc] + BN_EPS);
        float beta = bb[oc] - bm[oc] * inv;
        size_t base = (((size_t)n * COUT + oc) * HOUT + h) * HOUT + wbase;
#pragma unroll
        for (int i = 0; i < 7; i++) {
            float a = (j == 0) ? acc[i].x : (j == 1) ? acc[i].y
                    : (j == 2) ? acc[i].z : acc[i].w;
            float val = a * inv + beta;
            if (RELU) val = fmaxf(val, 0.f);
            out[base + i] = val;
        }
    }
}

// ---------------------------------------------------------------------------
// Shortcut: 1x1 conv stride 2 + BN, fused with residual add + ReLU into buf2.
// ---------------------------------------------------------------------------
__global__ __launch_bounds__(256)
void shortcut_bn_add(const float* __restrict__ x, const float* __restrict__ wq,
                     const float* __restrict__ bg, const float* __restrict__ bb,
                     const float* __restrict__ bm, const float* __restrict__ bv,
                     float* __restrict__ buf)
{
    __shared__ float s_x[CIN1 * HOUT];
    const int t = threadIdx.x;
    const int h = blockIdx.x;
    const int n = blockIdx.y;

    for (int idx = t; idx < CIN1 * HOUT; idx += 256) {
        int i = idx / HOUT;
        int w = idx - i * HOUT;
        s_x[idx] = x[(((size_t)n * CIN1 + i) * 56 + 2 * h) * 56 + 2 * w];
    }
    __syncthreads();

    const int oc = t;
    float acc[HOUT];
#pragma unroll
    for (int w = 0; w < HOUT; w++) acc[w] = 0.f;

    for (int i = 0; i < CIN1; i++) {
        float wv = wq[i * COUT + oc];
        const float* sp = &s_x[i * HOUT];
#pragma unroll
        for (int w = 0; w < HOUT; w++) acc[w] += wv * sp[w];
    }

    float inv  = bg[oc] * rsqrtf(bv[oc] + BN_EPS);
    float beta = bb[oc] - bm[oc] * inv;
    size_t base = (((size_t)n * COUT + oc) * HOUT + h) * HOUT;
#pragma unroll
    for (int w = 0; w < HOUT; w++) {
        float val = buf[base + w] + acc[w] * inv + beta;
        buf[base + w] = fmaxf(val, 0.f);
    }
}

// ---------------------------------------------------------------------------
// BFP activation quant: per (n, 32-ch block, h, w) shared pow2 exponent,
// 8-bit mantissa; exact exponent via frexpf, half-to-even rint.
// ---------------------------------------------------------------------------
__global__ __launch_bounds__(256)
void bfp_quant(const float* __restrict__ in, float* __restrict__ out)
{
    int tid = blockIdx.x * 256 + threadIdx.x;
    int hw = tid % HW;
    int cb = (tid / HW) & 7;
    int n  = tid / (HW * 8);

    size_t base = (((size_t)n * COUT + cb * 32) * HW) + hw;
    float v[32];
    float m = 0.f;
#pragma unroll
    for (int c = 0; c < 32; c++) {
        v[c] = in[base + (size_t)c * HW];
        m = fmaxf(m, fabsf(v[c]));
    }
    m = fmaxf(m, 1e-12f);
    int e;
    frexpf(m, &e);
    float scale = ldexpf(1.0f, e - 7);
#pragma unroll
    for (int c = 0; c < 32; c++) {
        float q = rintf(v[c] / scale);
        q = fminf(fmaxf(q, -128.f), 127.f);
        out[base + (size_t)c * HW] = q * scale;
    }
}

// ---------------------------------------------------------------------------
extern "C" void kernel_launch(void* const* d_in, const int* in_sizes, int n_in,
                              void* d_out, int out_size)
{
    const float* x  = (const float*)d_in[0];
    const float* w1 = (const float*)d_in[1];
    const float* w2 = (const float*)d_in[2];
    const float* ws = (const float*)d_in[3];
    const float* bn1_g = (const float*)d_in[4];
    const float* bn1_b = (const float*)d_in[5];
    const float* bn1_m = (const float*)d_in[6];
    const float* bn1_v = (const float*)d_in[7];
    const float* bn2_g = (const float*)d_in[8];
    const float* bn2_b = (const float*)d_in[9];
    const float* bn2_m = (const float*)d_in[10];
    const float* bn2_v = (const float*)d_in[11];
    const float* bns_g = (const float*)d_in[12];
    const float* bns_b = (const float*)d_in[13];
    const float* bns_m = (const float*)d_in[14];
    const float* bns_v = (const float*)d_in[15];
    float* out = (float*)d_out;

    float *wq1, *wq2, *wqs, *buf1, *buf2;
    cudaGetSymbolAddress((void**)&wq1,  g_wq1);
    cudaGetSymbolAddress((void**)&wq2,  g_wq2);
    cudaGetSymbolAddress((void**)&wqs,  g_wqs);
    cudaGetSymbolAddress((void**)&buf1, g_buf1);
    cudaGetSymbolAddress((void**)&buf2, g_buf2);

    // 1. weight quantization (+ transpose to [ic*9+tap][oc])
    quant_w3x3<<<(COUT * (CIN1/32) * 9 + 255) / 256, 256>>>(w1, wq1, CIN1, COUT);
    quant_w3x3<<<(COUT * (COUT/32) * 9 + 255) / 256, 256>>>(w2, wq2, COUT, COUT);
    quant_w1x1<<<(COUT * (CIN1/32) + 255) / 256, 256>>>(ws, wqs);

    // 2. conv1 (3x3, stride 2) + BN1 + ReLU
    conv3x3_bn<2, CIN1><<<dim3(COUT/128, HOUT/4, NB), 512>>>(
        x, wq1, bn1_g, bn1_b, bn1_m, bn1_v, buf1, 56, 1);

    // 3. BFP activation quant (in-place)
    bfp_quant<<<(NB * 8 * HW) / 256, 256>>>(buf1, buf1);

    // 4. conv2 (3x3, stride 1) + BN2
    conv3x3_bn<1, COUT><<<dim3(COUT/128, HOUT/4, NB), 512>>>(
        buf1, wq2, bn2_g, bn2_b, bn2_m, bn2_v, buf2, HOUT, 0);

    // 5. shortcut 1x1 stride-2 conv + BNs + add + ReLU (into buf2)
    shortcut_bn_add<<<dim3(HOUT, NB), 256>>>(
        x, wqs, bns_g, bns_b, bns_m, bns_v, buf2);

    // 6. final BFP activation quant -> out
    bfp_quant<<<(NB * 8 * HW) / 256, 256>>>(buf2, out);
}

// round 14
// speedup vs baseline: 1.1748x; 1.0734x over previous
#include <cuda_runtime.h>
#include <math.h>

// ---------------------------------------------------------------------------
// QuantBasicBlock: conv1(3x3,s2)+BN+ReLU+BFPq -> conv2(3x3,s1)+BN
//                  + shortcut(1x1,s2)+BN -> add -> ReLU -> BFPq
// Shapes: x(64,128,56,56), w1(256,128,3,3), w2(256,256,3,3), ws(256,128,1,1)
// out (64,256,28,28) fp32
// ---------------------------------------------------------------------------

#define NB    64
#define CIN1  128
#define COUT  256
#define HOUT  28
#define HW    (HOUT*HOUT)
#define BN_EPS 1e-5f

// Scratch (static device allocations; no cudaMalloc allowed)
__device__ __align__(16) float g_wq1[CIN1 * 9 * COUT];   // [ic*9+tap][oc]
__device__ __align__(16) float g_wq2[COUT * 9 * COUT];   // [ic*9+tap][oc]
__device__ __align__(16) float g_wqs[CIN1 * COUT];       // [ic][oc]
__device__ float g_buf1[(size_t)NB * COUT * HW];
__device__ float g_buf2[(size_t)NB * COUT * HW];

// ---------------- cp.async helpers ----------------
__device__ __forceinline__ unsigned smem_u32(const void* p) {
    return (unsigned)__cvta_generic_to_shared(p);
}
__device__ __forceinline__ void cp_async16(unsigned dst, const void* src) {
    asm volatile("cp.async.cg.shared.global [%0], [%1], 16;\n" :: "r"(dst), "l"(src));
}
// predicated 4B copy: pred=false -> zero-fill, no memory read
__device__ __forceinline__ void cp_async4_z(unsigned dst, const void* src, bool p) {
    int sz = p ? 4 : 0;
    asm volatile("cp.async.ca.shared.global [%0], [%1], 4, %2;\n"
                 :: "r"(dst), "l"(src), "r"(sz));
}
#define CP_COMMIT() asm volatile("cp.async.commit_group;\n" ::: "memory")
#define CP_WAIT(N)  asm volatile("cp.async.wait_group %0;\n" :: "n"(N) : "memory")

// ---------------------------------------------------------------------------
// Weight quantization (DSConv VQK): per (oc, 32-ic block, tap) scale = max/127,
// q = clip(rint(w/scale), -128, 127), store q*scale TRANSPOSED to [ic*9+tap][oc]
// ---------------------------------------------------------------------------
__global__ __launch_bounds__(256)
void quant_w3x3(const float* __restrict__ w, float* __restrict__ wq, int I, int O)
{
    int tid = blockIdx.x * blockDim.x + threadIdx.x;
    int IB = I / 32;
    int total = O * IB * 9;
    if (tid >= total) return;
    int tap = tid % 9;
    int ib  = (tid / 9) % IB;
    int o   = tid / (9 * IB);

    float v[32];
    float m = 0.f;
#pragma unroll
    for (int c = 0; c < 32; c++) {
        v[c] = w[((size_t)(o * I + ib * 32 + c)) * 9 + tap];
        m = fmaxf(m, fabsf(v[c]));
    }
    float scale = fmaxf(m, 1e-12f) * (1.0f / 127.0f);
#pragma unroll
    for (int c = 0; c < 32; c++) {
        float q = rintf(v[c] / scale);
        q = fminf(fmaxf(q, -128.f), 127.f);
        wq[((size_t)(ib * 32 + c) * 9 + tap) * O + o] = q * scale;
    }
}

__global__ __launch_bounds__(256)
void quant_w1x1(const float* __restrict__ w, float* __restrict__ wq)
{
    int tid = blockIdx.x * blockDim.x + threadIdx.x;
    if (tid >= COUT * (CIN1 / 32)) return;
    int ib = tid % (CIN1 / 32);
    int o  = tid / (CIN1 / 32);

    float v[32];
    float m = 0.f;
#pragma unroll
    for (int c = 0; c < 32; c++) {
        v[c] = w[o * CIN1 + ib * 32 + c];
        m = fmaxf(m, fabsf(v[c]));
    }
    float scale = fmaxf(m, 1e-12f) * (1.0f / 127.0f);
#pragma unroll
    for (int c = 0; c < 32; c++) {
        float q = rintf(v[c] / scale);
        q = fminf(fmaxf(q, -128.f), 127.f);
        wq[(ib * 32 + c) * COUT + o] = q * scale;
    }
}

// ---------------------------------------------------------------------------
// 3x3 conv + BN (+optional ReLU), 512 threads/block, cp.async double-buffered.
// Tile: 128 oc x 28 w x 4 h x 1 n. Warp w: hsub = w>>2, wgroup = w&3 (7 cols).
// Thread: 4 CONSECUTIVE oc (one LDS.128 per tap) x 7 w. Input window kept in
// registers per (icc,kh), reused across all 3 kw.
// Weight layout pre-transposed to [ic*9+tap][oc] -> vectorized fills.
// ---------------------------------------------------------------------------
template <int STRIDE, int CIN>
__global__ __launch_bounds__(512, 2)
void conv3x3_bn(const float* __restrict__ x, const float* __restrict__ wq,
                const float* __restrict__ bg, const float* __restrict__ bb,
                const float* __restrict__ bm, const float* __restrict__ bv,
                float* __restrict__ out, int HIN, int RELU)
{
    constexpr int ROWS = 3 * STRIDE + 3;              // input rows per tile
    constexpr int IWB  = (STRIDE == 2) ? 57 : 30;     // valid input cols (+pad)
    constexpr int IWP  = (STRIDE == 2) ? 60 : 32;     // padded row pitch
    constexpr int WSZ  = 6 * STRIDE + 3;              // register window size
    constexpr int NCHUNK = CIN / 4;
    constexpr int WELE = 4 * 9 * 32;                  // float4 weight elems/buf
    constexpr int IELE = 4 * ROWS * IWP;              // float input elems/buf

    extern __shared__ char dyn[];
    float4* s_w4 = (float4*)dyn;                      // [2][WELE]
    float*  s_in = (float*)(dyn + 2 * WELE * sizeof(float4));  // [2][IELE]

    const int t       = threadIdx.x;
    const int lane    = t & 31;
    const int warp    = t >> 5;
    const int hsub    = warp >> 2;
    const int wbase   = (warp & 3) * 7;
    const int oc_base = blockIdx.x * 128;
    const int h0      = blockIdx.y * 4;
    const int n       = blockIdx.z;
    const int WIN     = HIN;

    float4 acc[7];
#pragma unroll
    for (int i = 0; i < 7; i++) acc[i] = make_float4(0.f, 0.f, 0.f, 0.f);

    const float4* wq4 = (const float4*)wq;

    // issue async fills for ic chunk starting at ic0 into buffer `buf`
    auto issue = [&](int ic0, int buf) {
        const float4* wg = wq4 + (size_t)ic0 * 9 * (COUT / 4) + (oc_base >> 2);
        float4* wdst = s_w4 + buf * WELE;
#pragma unroll
        for (int k = t; k < WELE; k += 512)
            cp_async16(smem_u32(wdst + k), wg + (size_t)(k >> 5) * (COUT / 4) + (k & 31));
        float* idst = s_in + buf * IELE;
        for (int idx = t; idx < 4 * ROWS * IWB; idx += 512) {
            int icc = idx / (ROWS * IWB);
            int rem = idx - icc * (ROWS * IWB);
            int r   = rem / IWB;
            int j   = rem - r * IWB;
            int ih  = h0 * STRIDE + r - 1;
            int iw  = j - 1;
            bool p  = (ih >= 0 && ih < HIN && iw >= 0 && iw < WIN);
            const float* src = x + (((size_t)n * CIN + ic0 + icc) * HIN + ih) * WIN + iw;
            cp_async4_z(smem_u32(idst + (icc * ROWS + r) * IWP + j), src, p);
        }
        CP_COMMIT();
    };

    issue(0, 0);

    for (int c = 0; c < NCHUNK; c++) {
        if (c + 1 < NCHUNK) {
            issue((c + 1) * 4, (c + 1) & 1);
            CP_WAIT(1);                // wait for chunk c, leave c+1 in flight
        } else {
            CP_WAIT(0);
        }
        __syncthreads();

        const float4* wb = s_w4 + (c & 1) * WELE;
        const float*  ib = s_in + (c & 1) * IELE;

#pragma unroll
        for (int icc = 0; icc < 4; icc++) {
#pragma unroll
            for (int kh = 0; kh < 3; kh++) {
                const float* sp =
                    &ib[(icc * ROWS + hsub * STRIDE + kh) * IWP + wbase * STRIDE];
                float win[WSZ];
#pragma unroll
                for (int j = 0; j < WSZ; j++) win[j] = sp[j];
#pragma unroll
                for (int kw = 0; kw < 3; kw++) {
                    float4 wv = wb[(icc * 9 + kh * 3 + kw) * 32 + lane];
#pragma unroll
                    for (int i = 0; i < 7; i++) {
                        float xv = win[i * STRIDE + kw];
                        acc[i].x += wv.x * xv;
                        acc[i].y += wv.y * xv;
                        acc[i].z += wv.z * xv;
                        acc[i].w += wv.w * xv;
                    }
                }
            }
        }
        // guard buffer reuse: next iteration's issue() overwrites this buffer's
        // sibling, which was read in the previous iteration
        if (c + 1 < NCHUNK) __syncthreads();
    }

    // epilogue: BN (+ReLU)
    const int h = h0 + hsub;
#pragma unroll
    for (int j = 0; j < 4; j++) {
        int oc = oc_base + lane * 4 + j;
        float inv  = bg[oc] * rsqrtf(bv[oc] + BN_EPS);
        float beta = bb[oc] - bm[oc] * inv;
        size_t base = (((size_t)n * COUT + oc) * HOUT + h) * HOUT + wbase;
#pragma unroll
        for (int i = 0; i < 7; i++) {
            float a = (j == 0) ? acc[i].x : (j == 1) ? acc[i].y
                    : (j == 2) ? acc[i].z : acc[i].w;
            float val = a * inv + beta;
            if (RELU) val = fmaxf(val, 0.f);
            out[base + i] = val;
        }
    }
}

// ---------------------------------------------------------------------------
// Shortcut: 1x1 conv stride 2 + BN, fused with residual add + ReLU into buf2.
// ---------------------------------------------------------------------------
__global__ __launch_bounds__(256)
void shortcut_bn_add(const float* __restrict__ x, const float* __restrict__ wq,
                     const float* __restrict__ bg, const float* __restrict__ bb,
                     const float* __restrict__ bm, const float* __restrict__ bv,
                     float* __restrict__ buf)
{
    __shared__ float s_x[CIN1 * HOUT];
    const int t = threadIdx.x;
    const int h = blockIdx.x;
    const int n = blockIdx.y;

    for (int idx = t; idx < CIN1 * HOUT; idx += 256) {
        int i = idx / HOUT;
        int w = idx - i * HOUT;
        s_x[idx] = x[(((size_t)n * CIN1 + i) * 56 + 2 * h) * 56 + 2 * w];
    }
    __syncthreads();

    const int oc = t;
    float acc[HOUT];
#pragma unroll
    for (int w = 0; w < HOUT; w++) acc[w] = 0.f;

    for (int i = 0; i < CIN1; i++) {
        float wv = wq[i * COUT + oc];
        const float* sp = &s_x[i * HOUT];
#pragma unroll
        for (int w = 0; w < HOUT; w++) acc[w] += wv * sp[w];
    }

    float inv  = bg[oc] * rsqrtf(bv[oc] + BN_EPS);
    float beta = bb[oc] - bm[oc] * inv;
    size_t base = (((size_t)n * COUT + oc) * HOUT + h) * HOUT;
#pragma unroll
    for (int w = 0; w < HOUT; w++) {
        float val = buf[base + w] + acc[w] * inv + beta;
        buf[base + w] = fmaxf(val, 0.f);
    }
}

// ---------------------------------------------------------------------------
// BFP activation quant: per (n, 32-ch block, h, w) shared pow2 exponent,
// 8-bit mantissa; exact exponent via frexpf, half-to-even rint.
// ---------------------------------------------------------------------------
__global__ __launch_bounds__(256)
void bfp_quant(const float* __restrict__ in, float* __restrict__ out)
{
    int tid = blockIdx.x * 256 + threadIdx.x;
    int hw = tid % HW;
    int cb = (tid / HW) & 7;
    int n  = tid / (HW * 8);

    size_t base = (((size_t)n * COUT + cb * 32) * HW) + hw;
    float v[32];
    float m = 0.f;
#pragma unroll
    for (int c = 0; c < 32; c++) {
        v[c] = in[base + (size_t)c * HW];
        m = fmaxf(m, fabsf(v[c]));
    }
    m = fmaxf(m, 1e-12f);
    int e;
    frexpf(m, &e);
    float scale = ldexpf(1.0f, e - 7);
#pragma unroll
    for (int c = 0; c < 32; c++) {
        float q = rintf(v[c] / scale);
        q = fminf(fmaxf(q, -128.f), 127.f);
        out[base + (size_t)c * HW] = q * scale;
    }
}

// ---------------------------------------------------------------------------
extern "C" void kernel_launch(void* const* d_in, const int* in_sizes, int n_in,
                              void* d_out, int out_size)
{
    const float* x  = (const float*)d_in[0];
    const float* w1 = (const float*)d_in[1];
    const float* w2 = (const float*)d_in[2];
    const float* ws = (const float*)d_in[3];
    const float* bn1_g = (const float*)d_in[4];
    const float* bn1_b = (const float*)d_in[5];
    const float* bn1_m = (const float*)d_in[6];
    const float* bn1_v = (const float*)d_in[7];
    const float* bn2_g = (const float*)d_in[8];
    const float* bn2_b = (const float*)d_in[9];
    const float* bn2_m = (const float*)d_in[10];
    const float* bn2_v = (const float*)d_in[11];
    const float* bns_g = (const float*)d_in[12];
    const float* bns_b = (const float*)d_in[13];
    const float* bns_m = (const float*)d_in[14];
    const float* bns_v = (const float*)d_in[15];
    float* out = (float*)d_out;

    float *wq1, *wq2, *wqs, *buf1, *buf2;
    cudaGetSymbolAddress((void**)&wq1,  g_wq1);
    cudaGetSymbolAddress((void**)&wq2,  g_wq2);
    cudaGetSymbolAddress((void**)&wqs,  g_wqs);
    cudaGetSymbolAddress((void**)&buf1, g_buf1);
    cudaGetSymbolAddress((void**)&buf2, g_buf2);

    // dynamic smem sizes (double-buffered)
    const int SMEM_W  = 2 * 4 * 9 * 32 * 16;                 // 36864
    const int SMEM_C1 = SMEM_W + 2 * 4 * 9 * 60 * 4;         // 54144
    const int SMEM_C2 = SMEM_W + 2 * 4 * 6 * 32 * 4;         // 43008
    cudaFuncSetAttribute(conv3x3_bn<2, CIN1>,
                         cudaFuncAttributeMaxDynamicSharedMemorySize, SMEM_C1);
    cudaFuncSetAttribute(conv3x3_bn<1, COUT>,
                         cudaFuncAttributeMaxDynamicSharedMemorySize, SMEM_C2);

    // 1. weight quantization (+ transpose to [ic*9+tap][oc])
    quant_w3x3<<<(COUT * (CIN1/32) * 9 + 255) / 256, 256>>>(w1, wq1, CIN1, COUT);
    quant_w3x3<<<(COUT * (COUT/32) * 9 + 255) / 256, 256>>>(w2, wq2, COUT, COUT);
    quant_w1x1<<<(COUT * (CIN1/32) + 255) / 256, 256>>>(ws, wqs);

    // 2. conv1 (3x3, stride 2) + BN1 + ReLU
    conv3x3_bn<2, CIN1><<<dim3(COUT/128, HOUT/4, NB), 512, SMEM_C1>>>(
        x, wq1, bn1_g, bn1_b, bn1_m, bn1_v, buf1, 56, 1);

    // 3. BFP activation quant (in-place)
    bfp_quant<<<(NB * 8 * HW) / 256, 256>>>(buf1, buf1);

    // 4. conv2 (3x3, stride 1) + BN2
    conv3x3_bn<1, COUT><<<dim3(COUT/128, HOUT/4, NB), 512, SMEM_C2>>>(
        buf1, wq2, bn2_g, bn2_b, bn2_m, bn2_v, buf2, HOUT, 0);

    // 5. shortcut 1x1 stride-2 conv + BNs + add + ReLU (into buf2)
    shortcut_bn_add<<<dim3(HOUT, NB), 256>>>(
        x, wqs, bns_g, bns_b, bns_m, bns_v, buf2);

    // 6. final BFP activation quant -> out
    bfp_quant<<<(NB * 8 * HW) / 256, 256>>>(buf2, out);
}